// round 1
// baseline (speedup 1.0000x reference)
#include <cuda_runtime.h>
#include <math.h>

// Problem constants (GymNetwork): B=262144, D=128, G=8, F=80, A=18
constexpr int D = 128;
constexpr int G = 8;
constexpr int F = 80;
constexpr int A = 18;

constexpr int BM      = 128;   // rows (samples) per block
constexpr int THREADS = 256;   // 16 mt x 16 nt, each thread 8m x 5n
constexpr int TM = 8;
constexpr int TN = 5;

constexpr int SA_STRIDE = 132; // state tile row stride (pad vs 128)
constexpr int SH_STRIDE = 84;  // h tile row stride (pad vs 80)

// shared memory layout (in floats)
constexpr int OFF_A  = 0;                       // state tile / later h2: BM*SA_STRIDE
constexpr int OFF_H1 = BM * SA_STRIDE;          // h1 / h3: BM*SH_STRIDE
constexpr int OFF_W  = OFF_H1 + BM * SH_STRIDE; // weight tile: up to D*F
constexpr int SMEM_FLOATS = OFF_W + D * F;
constexpr int SMEM_BYTES  = SMEM_FLOATS * 4 + BM * 4; // + idx ints

// Pre-transposed weights (device scratch; no allocation at kernel_launch time)
__device__ float g_W1t[G * D * F]; // [g][d][f]  = W1[g][f][d]
__device__ float g_W2t[F * F];     // [k][n]     = W2[n][k]
__device__ float g_W3t[F * F];     // [k][n]     = W3[n][k]
__device__ float g_W4t[G * F * A]; // [g][k][a]  = W4[g][a][k]

__global__ void prep_kernel(const float* __restrict__ W1, const float* __restrict__ W2,
                            const float* __restrict__ W3, const float* __restrict__ W4) {
    int i = blockIdx.x * blockDim.x + threadIdx.x;
    if (i < G * D * F) {
        int g = i / (D * F);
        int r = i - g * (D * F);
        int d = r / F;
        int f = r - d * F;
        g_W1t[i] = W1[(g * F + f) * D + d];
    }
    if (i < F * F) {
        int k = i / F;
        int n = i - k * F;
        g_W2t[i] = W2[n * F + k];
        g_W3t[i] = W3[n * F + k];
    }
    if (i < G * F * A) {
        int g = i / (F * A);
        int r = i - g * (F * A);
        int k = r / A;
        int a = r - k * A;
        g_W4t[i] = W4[(g * A + a) * F + k];
    }
}

__global__ __launch_bounds__(THREADS, 1)
void fused_kernel(const float* __restrict__ state, const int* __restrict__ idx,
                  const float* __restrict__ b1, const float* __restrict__ b2,
                  const float* __restrict__ b3, const float* __restrict__ b4,
                  float* __restrict__ out, int nTotal) {
    extern __shared__ float sm[];
    float* sA  = sm + OFF_A;   // state tile, [m][k] stride SA_STRIDE; later reused as h2
    float* sH1 = sm + OFF_H1;  // h1 / h3, [m][k] stride SH_STRIDE
    float* sW  = sm + OFF_W;   // current layer's B matrix, [k][n]
    int*   sIdx = (int*)(sm + SMEM_FLOATS);

    const int tid   = threadIdx.x;
    const int mBase = blockIdx.x * BM;
    const int mt = tid >> 4;      // 0..15
    const int nt = tid & 15;      // 0..15
    const int m0 = mt * TM;
    const int n0 = nt * TN;

    const int nValid = min(BM, nTotal - mBase);

    // --- load routing indices ---
    if (tid < BM) sIdx[tid] = (tid < nValid) ? idx[mBase + tid] : -1;

    // --- load state tile (128 x 128 f32, float4 coalesced) ---
    {
        const float4* src = (const float4*)(state + (size_t)mBase * D);
        #pragma unroll
        for (int it = 0; it < (BM * D / 4) / THREADS; ++it) {
            int flat = tid + it * THREADS;         // 0..4095
            int m  = flat >> 5;                     // row
            int k4 = flat & 31;                     // float4 col
            if (m < nValid) {
                float4 v = src[flat];
                *(float4*)(sA + m * SA_STRIDE + k4 * 4) = v;
            }
        }
    }
    __syncthreads();

    const int gLo = sIdx[0];
    const int gHi = sIdx[nValid - 1];

    // ================= Layer 1: h1 = relu(state @ W1[g]^T + b1[g]) =================
    for (int g = gLo; g <= gHi; ++g) {
        __syncthreads(); // prior sW readers done (no-op cost on first iter)
        {
            const float4* src = (const float4*)(g_W1t + g * D * F);
            float4* dst = (float4*)sW;
            for (int it = tid; it < D * F / 4; it += THREADS) dst[it] = src[it];
        }
        __syncthreads();

        float acc[TM][TN];
        #pragma unroll
        for (int i = 0; i < TM; ++i)
            #pragma unroll
            for (int j = 0; j < TN; ++j)
                acc[i][j] = __ldg(&b1[g * F + n0 + j]);

        #pragma unroll 4
        for (int k = 0; k < D; ++k) {
            float a[TM], bb[TN];
            #pragma unroll
            for (int i = 0; i < TM; ++i) a[i] = sA[(m0 + i) * SA_STRIDE + k];
            #pragma unroll
            for (int j = 0; j < TN; ++j) bb[j] = sW[k * F + n0 + j];
            #pragma unroll
            for (int i = 0; i < TM; ++i)
                #pragma unroll
                for (int j = 0; j < TN; ++j)
                    acc[i][j] = fmaf(a[i], bb[j], acc[i][j]);
        }
        #pragma unroll
        for (int i = 0; i < TM; ++i) {
            if (sIdx[m0 + i] == g) {
                #pragma unroll
                for (int j = 0; j < TN; ++j)
                    sH1[(m0 + i) * SH_STRIDE + n0 + j] = fmaxf(acc[i][j], 0.0f);
            }
        }
    }
    __syncthreads();

    // ================= Layer 2: h2 = relu(h1 @ W2^T + b2) -> sA region =================
    {
        const float4* src = (const float4*)g_W2t;
        float4* dst = (float4*)sW;
        for (int it = tid; it < F * F / 4; it += THREADS) dst[it] = src[it];
    }
    __syncthreads();
    {
        float acc[TM][TN];
        #pragma unroll
        for (int i = 0; i < TM; ++i)
            #pragma unroll
            for (int j = 0; j < TN; ++j)
                acc[i][j] = __ldg(&b2[n0 + j]);
        #pragma unroll 4
        for (int k = 0; k < F; ++k) {
            float a[TM], bb[TN];
            #pragma unroll
            for (int i = 0; i < TM; ++i) a[i] = sH1[(m0 + i) * SH_STRIDE + k];
            #pragma unroll
            for (int j = 0; j < TN; ++j) bb[j] = sW[k * F + n0 + j];
            #pragma unroll
            for (int i = 0; i < TM; ++i)
                #pragma unroll
                for (int j = 0; j < TN; ++j)
                    acc[i][j] = fmaf(a[i], bb[j], acc[i][j]);
        }
        __syncthreads(); // everyone finished reading sH1 & sW
        #pragma unroll
        for (int i = 0; i < TM; ++i)
            #pragma unroll
            for (int j = 0; j < TN; ++j)
                sA[(m0 + i) * SH_STRIDE + n0 + j] = fmaxf(acc[i][j], 0.0f); // h2 in sA region
    }
    __syncthreads();

    // ================= Layer 3: h3 = relu(h2 @ W3^T + b3) -> sH1 =================
    {
        const float4* src = (const float4*)g_W3t;
        float4* dst = (float4*)sW;
        for (int it = tid; it < F * F / 4; it += THREADS) dst[it] = src[it];
    }
    __syncthreads();
    {
        float acc[TM][TN];
        #pragma unroll
        for (int i = 0; i < TM; ++i)
            #pragma unroll
            for (int j = 0; j < TN; ++j)
                acc[i][j] = __ldg(&b3[n0 + j]);
        #pragma unroll 4
        for (int k = 0; k < F; ++k) {
            float a[TM], bb[TN];
            #pragma unroll
            for (int i = 0; i < TM; ++i) a[i] = sA[(m0 + i) * SH_STRIDE + k];
            #pragma unroll
            for (int j = 0; j < TN; ++j) bb[j] = sW[k * F + n0 + j];
            #pragma unroll
            for (int i = 0; i < TM; ++i)
                #pragma unroll
                for (int j = 0; j < TN; ++j)
                    acc[i][j] = fmaf(a[i], bb[j], acc[i][j]);
        }
        __syncthreads();
        #pragma unroll
        for (int i = 0; i < TM; ++i)
            #pragma unroll
            for (int j = 0; j < TN; ++j)
                sH1[(m0 + i) * SH_STRIDE + n0 + j] = fmaxf(acc[i][j], 0.0f);
    }
    __syncthreads();

    // ================= Layer 4: out = h3 @ W4[g]^T + b4[g] (per game) =================
    const int n4 = nt * 2; // 2 output columns per thread; nt>=9 idle
    for (int g = gLo; g <= gHi; ++g) {
        __syncthreads();
        {
            const float4* src = (const float4*)(g_W4t + g * F * A);
            float4* dst = (float4*)sW;
            for (int it = tid; it < F * A / 4; it += THREADS) dst[it] = src[it];
        }
        __syncthreads();

        if (n4 < A) {
            float acc[TM][2];
            #pragma unroll
            for (int i = 0; i < TM; ++i) {
                acc[i][0] = __ldg(&b4[g * A + n4]);
                acc[i][1] = __ldg(&b4[g * A + n4 + 1]);
            }
            #pragma unroll 4
            for (int k = 0; k < F; ++k) {
                float bb0 = sW[k * A + n4];
                float bb1 = sW[k * A + n4 + 1];
                #pragma unroll
                for (int i = 0; i < TM; ++i) {
                    float a = sH1[(m0 + i) * SH_STRIDE + k];
                    acc[i][0] = fmaf(a, bb0, acc[i][0]);
                    acc[i][1] = fmaf(a, bb1, acc[i][1]);
                }
            }
            #pragma unroll
            for (int i = 0; i < TM; ++i) {
                if (sIdx[m0 + i] == g) {
                    size_t o = (size_t)(mBase + m0 + i) * A + n4;
                    out[o]     = acc[i][0];
                    out[o + 1] = acc[i][1];
                }
            }
        }
    }
}

extern "C" void kernel_launch(void* const* d_in, const int* in_sizes, int n_in,
                              void* d_out, int out_size) {
    const float* state = (const float*)d_in[0];
    const int*   idx   = (const int*)d_in[1];
    const float* W1    = (const float*)d_in[2];
    const float* b1    = (const float*)d_in[3];
    const float* W2    = (const float*)d_in[4];
    const float* b2    = (const float*)d_in[5];
    const float* W3    = (const float*)d_in[6];
    const float* b3    = (const float*)d_in[7];
    const float* W4    = (const float*)d_in[8];
    const float* b4    = (const float*)d_in[9];
    float* out = (float*)d_out;

    const int B = in_sizes[1]; // idx element count

    // Pre-transpose weights (tiny; same stream => ordered before fused kernel)
    int prepN = G * D * F; // 81920, the largest
    prep_kernel<<<(prepN + 255) / 256, 256>>>(W1, W2, W3, W4);

    static_assert(SMEM_BYTES < 230 * 1024, "smem budget");
    cudaFuncSetAttribute(fused_kernel, cudaFuncAttributeMaxDynamicSharedMemorySize, SMEM_BYTES);

    int grid = (B + BM - 1) / BM;
    fused_kernel<<<grid, THREADS, SMEM_BYTES>>>(state, idx, b1, b2, b3, b4, out, B);
}

// round 2
// speedup vs baseline: 2.0383x; 2.0383x over previous
#include <cuda_runtime.h>
#include <math.h>

// GymNetwork: B=262144, D=128, G=8, F=80, A=18
constexpr int D = 128;
constexpr int G = 8;
constexpr int F = 80;
constexpr int A = 18;

constexpr int BM      = 128;   // samples per block
constexpr int THREADS = 256;   // 16 mt x 16 nt
constexpr int TM = 8;
constexpr int TN = 5;

constexpr int KS1  = 68;   // layer-1 half-K tile stride (64 + 4 pad), floats
constexpr int HS   = 84;   // hidden tile stride (80 + 4 pad)
constexpr int WS23 = 44;   // W2/W3 half-K stride (40 + 4 pad)

// smem layout (floats)
constexpr int OFF_R0   = 0;              // state-half (stride KS1) / h2 (stride HS)
constexpr int OFF_R1   = BM * HS;        // h1 / h3 (stride HS)
constexpr int OFF_W    = 2 * BM * HS;    // weight tile
constexpr int W_FLOATS = F * KS1;        // 5440 = max(80*68, 80*44, 18*84)
constexpr int OFF_IDX  = OFF_W + W_FLOATS;
constexpr int SMEM_FLOATS = OFF_IDX + BM;
constexpr int SMEM_BYTES  = SMEM_FLOATS * 4;   // 108288 B -> 2 CTAs/SM

__global__ __launch_bounds__(THREADS, 2)
void fused_kernel(const float* __restrict__ state, const int* __restrict__ idx,
                  const float* __restrict__ W1, const float* __restrict__ b1,
                  const float* __restrict__ W2, const float* __restrict__ b2,
                  const float* __restrict__ W3, const float* __restrict__ b3,
                  const float* __restrict__ W4, const float* __restrict__ b4,
                  float* __restrict__ out, int nTotal)
{
    extern __shared__ float sm[];
    float* R0 = sm + OFF_R0;
    float* R1 = sm + OFF_R1;
    float* sW = sm + OFF_W;
    int*   sIdx = (int*)(sm + OFF_IDX);

    const int tid   = threadIdx.x;
    const int mBase = blockIdx.x * BM;
    const int mt = tid >> 4;
    const int nt = tid & 15;
    const int m0 = mt * TM;
    const int n0 = nt * TN;
    const int nValid = min(BM, nTotal - mBase);

    if (tid < BM) sIdx[tid] = (tid < nValid) ? idx[mBase + tid] : -1;
    __syncthreads();
    const int gLo = sIdx[0];
    const int gHi = sIdx[nValid - 1];

    // ================= Layer 1: h1 = relu(state @ W1[g]^T + b1[g]) -> R1 =================
    for (int g = gLo; g <= gHi; ++g) {
        float acc[TM][TN];
        #pragma unroll
        for (int j = 0; j < TN; ++j) {
            float bv = __ldg(&b1[g * F + n0 + j]);
            #pragma unroll
            for (int i = 0; i < TM; ++i) acc[i][j] = bv;
        }

        for (int h = 0; h < 2; ++h) {
            __syncthreads(); // prior consumers of R0/sW done
            // stage state k-half: 128 rows x 64 floats -> stride KS1
            {
                const float4* src = (const float4*)state;
                float4* dst = (float4*)R0;
                #pragma unroll
                for (int it = tid; it < BM * 16; it += THREADS) {
                    int m = it >> 4, c = it & 15;
                    float4 v = (m < nValid) ? src[(size_t)(mBase + m) * 32 + h * 16 + c]
                                            : make_float4(0.f, 0.f, 0.f, 0.f);
                    dst[m * (KS1 / 4) + c] = v;
                }
            }
            // stage W1[g] k-half: 80 rows x 64 floats -> stride KS1 ([n][k], native layout)
            {
                const float4* src = (const float4*)W1;
                float4* dst = (float4*)sW;
                #pragma unroll
                for (int it = tid; it < F * 16; it += THREADS) {
                    int n = it >> 4, c = it & 15;
                    dst[n * (KS1 / 4) + c] = src[(size_t)(g * F + n) * 32 + h * 16 + c];
                }
            }
            __syncthreads();

            const float4* A4 = (const float4*)R0;
            const float4* B4 = (const float4*)sW;
            #pragma unroll 2
            for (int k = 0; k < 16; ++k) {
                float4 b[TN];
                #pragma unroll
                for (int j = 0; j < TN; ++j) b[j] = B4[(n0 + j) * (KS1 / 4) + k];
                #pragma unroll
                for (int i = 0; i < TM; ++i) {
                    float4 a = A4[(m0 + i) * (KS1 / 4) + k];
                    #pragma unroll
                    for (int j = 0; j < TN; ++j) {
                        acc[i][j] = fmaf(a.x, b[j].x, acc[i][j]);
                        acc[i][j] = fmaf(a.y, b[j].y, acc[i][j]);
                        acc[i][j] = fmaf(a.z, b[j].z, acc[i][j]);
                        acc[i][j] = fmaf(a.w, b[j].w, acc[i][j]);
                    }
                }
            }
        }
        #pragma unroll
        for (int i = 0; i < TM; ++i) {
            if (sIdx[m0 + i] == g) {
                #pragma unroll
                for (int j = 0; j < TN; ++j)
                    R1[(m0 + i) * HS + n0 + j] = fmaxf(acc[i][j], 0.f);
            }
        }
    }

    // ================= Layer 2: h2 = relu(h1 @ W2^T + b2) -> R0 =================
    {
        float acc[TM][TN];
        #pragma unroll
        for (int j = 0; j < TN; ++j) {
            float bv = __ldg(&b2[n0 + j]);
            #pragma unroll
            for (int i = 0; i < TM; ++i) acc[i][j] = bv;
        }
        for (int h = 0; h < 2; ++h) {
            __syncthreads(); // h1 writes done (h==0) / prior sW readers done
            { // stage W2 k-half: 80 rows x 40 floats ([n][k] native) -> stride WS23
                const float4* src = (const float4*)W2;
                float4* dst = (float4*)sW;
                #pragma unroll
                for (int it = tid; it < F * 10; it += THREADS) {
                    int n = it / 10, c = it - n * 10;
                    dst[n * (WS23 / 4) + c] = src[n * 20 + h * 10 + c];
                }
            }
            __syncthreads();
            const float4* A4 = (const float4*)R1;
            const float4* B4 = (const float4*)sW;
            #pragma unroll 2
            for (int k = 0; k < 10; ++k) {
                float4 b[TN];
                #pragma unroll
                for (int j = 0; j < TN; ++j) b[j] = B4[(n0 + j) * (WS23 / 4) + k];
                #pragma unroll
                for (int i = 0; i < TM; ++i) {
                    float4 a = A4[(m0 + i) * (HS / 4) + h * 10 + k];
                    #pragma unroll
                    for (int j = 0; j < TN; ++j) {
                        acc[i][j] = fmaf(a.x, b[j].x, acc[i][j]);
                        acc[i][j] = fmaf(a.y, b[j].y, acc[i][j]);
                        acc[i][j] = fmaf(a.z, b[j].z, acc[i][j]);
                        acc[i][j] = fmaf(a.w, b[j].w, acc[i][j]);
                    }
                }
            }
        }
        #pragma unroll
        for (int i = 0; i < TM; ++i)
            #pragma unroll
            for (int j = 0; j < TN; ++j)
                R0[(m0 + i) * HS + n0 + j] = fmaxf(acc[i][j], 0.f);
    }

    // ================= Layer 3: h3 = relu(h2 @ W3^T + b3) -> R1 =================
    {
        float acc[TM][TN];
        #pragma unroll
        for (int j = 0; j < TN; ++j) {
            float bv = __ldg(&b3[n0 + j]);
            #pragma unroll
            for (int i = 0; i < TM; ++i) acc[i][j] = bv;
        }
        for (int h = 0; h < 2; ++h) {
            __syncthreads();
            {
                const float4* src = (const float4*)W3;
                float4* dst = (float4*)sW;
                #pragma unroll
                for (int it = tid; it < F * 10; it += THREADS) {
                    int n = it / 10, c = it - n * 10;
                    dst[n * (WS23 / 4) + c] = src[n * 20 + h * 10 + c];
                }
            }
            __syncthreads();
            const float4* A4 = (const float4*)R0;
            const float4* B4 = (const float4*)sW;
            #pragma unroll 2
            for (int k = 0; k < 10; ++k) {
                float4 b[TN];
                #pragma unroll
                for (int j = 0; j < TN; ++j) b[j] = B4[(n0 + j) * (WS23 / 4) + k];
                #pragma unroll
                for (int i = 0; i < TM; ++i) {
                    float4 a = A4[(m0 + i) * (HS / 4) + h * 10 + k];
                    #pragma unroll
                    for (int j = 0; j < TN; ++j) {
                        acc[i][j] = fmaf(a.x, b[j].x, acc[i][j]);
                        acc[i][j] = fmaf(a.y, b[j].y, acc[i][j]);
                        acc[i][j] = fmaf(a.z, b[j].z, acc[i][j]);
                        acc[i][j] = fmaf(a.w, b[j].w, acc[i][j]);
                    }
                }
            }
        }
        __syncthreads(); // all layer-2 reads of R1 (h1) complete before overwrite
        #pragma unroll
        for (int i = 0; i < TM; ++i)
            #pragma unroll
            for (int j = 0; j < TN; ++j)
                R1[(m0 + i) * HS + n0 + j] = fmaxf(acc[i][j], 0.f);
    }

    // ================= Layer 4: out = h3 @ W4[g]^T + b4[g] =================
    const int n4 = nt * 2; // 2 output cols per thread; nt >= 9 idle in compute
    for (int g = gLo; g <= gHi; ++g) {
        __syncthreads(); // h3 writes done (first g) / prior sW readers done
        { // stage W4[g]: 18 rows x 80 floats ([n][k] native) -> stride HS
            const float4* src = (const float4*)W4;
            float4* dst = (float4*)sW;
            #pragma unroll
            for (int it = tid; it < A * 20; it += THREADS) {
                int n = it / 20, c = it - n * 20;
                dst[n * (HS / 4) + c] = src[(size_t)(g * A + n) * 20 + c];
            }
        }
        __syncthreads();

        if (n4 < A) {
            float acc0[TM], acc1[TM];
            float bv0 = __ldg(&b4[g * A + n4]);
            float bv1 = __ldg(&b4[g * A + n4 + 1]);
            #pragma unroll
            for (int i = 0; i < TM; ++i) { acc0[i] = bv0; acc1[i] = bv1; }

            const float4* A4 = (const float4*)R1;
            const float4* B4 = (const float4*)sW;
            #pragma unroll 2
            for (int k = 0; k < 20; ++k) {
                float4 c0 = B4[n4 * (HS / 4) + k];
                float4 c1 = B4[(n4 + 1) * (HS / 4) + k];
                #pragma unroll
                for (int i = 0; i < TM; ++i) {
                    float4 a = A4[(m0 + i) * (HS / 4) + k];
                    acc0[i] = fmaf(a.x, c0.x, acc0[i]);
                    acc0[i] = fmaf(a.y, c0.y, acc0[i]);
                    acc0[i] = fmaf(a.z, c0.z, acc0[i]);
                    acc0[i] = fmaf(a.w, c0.w, acc0[i]);
                    acc1[i] = fmaf(a.x, c1.x, acc1[i]);
                    acc1[i] = fmaf(a.y, c1.y, acc1[i]);
                    acc1[i] = fmaf(a.z, c1.z, acc1[i]);
                    acc1[i] = fmaf(a.w, c1.w, acc1[i]);
                }
            }
            #pragma unroll
            for (int i = 0; i < TM; ++i) {
                if (sIdx[m0 + i] == g) {
                    float2 v = make_float2(acc0[i], acc1[i]);
                    *(float2*)(out + (size_t)(mBase + m0 + i) * A + n4) = v;
                }
            }
        }
    }
}

extern "C" void kernel_launch(void* const* d_in, const int* in_sizes, int n_in,
                              void* d_out, int out_size) {
    const float* state = (const float*)d_in[0];
    const int*   idx   = (const int*)d_in[1];
    const float* W1    = (const float*)d_in[2];
    const float* b1    = (const float*)d_in[3];
    const float* W2    = (const float*)d_in[4];
    const float* b2    = (const float*)d_in[5];
    const float* W3    = (const float*)d_in[6];
    const float* b3    = (const float*)d_in[7];
    const float* W4    = (const float*)d_in[8];
    const float* b4    = (const float*)d_in[9];
    float* out = (float*)d_out;

    const int B = in_sizes[1]; // idx element count

    static_assert(SMEM_BYTES <= 110 * 1024, "smem budget for 2 CTAs/SM");
    cudaFuncSetAttribute(fused_kernel, cudaFuncAttributeMaxDynamicSharedMemorySize, SMEM_BYTES);

    int grid = (B + BM - 1) / BM;
    fused_kernel<<<grid, THREADS, SMEM_BYTES>>>(state, idx, W1, b1, W2, b2, W3, b3,
                                                W4, b4, out, B);
}